// round 2
// baseline (speedup 1.0000x reference)
#include <cuda_runtime.h>
#include <math.h>

#define N_NODES 50000
#define E_RAW   800000
#define E_TOT   850000   // E_RAW + N_NODES self loops
#define FEAT    120
#define TOPOF   8
#define K1      128      // FEAT + TOPOF
#define F1      64       // H1*D1
#define H1      8
#define D1      8
#define C       40
#define NEG_SLOPE 0.2f

// ---------------- scratch (device globals; no allocs allowed) ----------------
__device__ float g_h1  [N_NODES * F1];   // layer1 linear output [N, 8, 8]
__device__ float g_als1[N_NODES * H1];
__device__ float g_ald1[N_NODES * H1];
__device__ float g_m1  [N_NODES * H1];   // per (dst, head) max logit
__device__ float g_s1  [N_NODES * H1];   // per (dst, head) sum of p
__device__ float g_out1[N_NODES * F1];   // layer1 aggregation, then h2 = elu(.)
__device__ float g_h2  [N_NODES * C];    // layer2 linear output
__device__ float g_als2[N_NODES];
__device__ float g_ald2[N_NODES];
__device__ float g_m2  [N_NODES];
__device__ float g_s2  [N_NODES];

// ---------------- helpers ----------------
__device__ __forceinline__ float lrelu(float x) { return x > 0.f ? x : NEG_SLOPE * x; }

__device__ __forceinline__ void atomic_max_f(float* a, float v) {
    if (v >= 0.f) atomicMax((int*)a, __float_as_int(v));
    else          atomicMin((unsigned int*)a, __float_as_uint(v));
}

__device__ __forceinline__ void edge_sd(const int* __restrict__ ei, int e, int& s, int& d) {
    if (e < E_RAW) { s = ei[e]; d = ei[E_RAW + e]; }
    else           { s = e - E_RAW; d = s; }      // self loop
}

// ---------------- kernels ----------------

// Zero accumulators, set maxes to -inf, zero d_out (it is poisoned 0xAA).
__global__ void k_init(float* __restrict__ out) {
    int i = blockIdx.x * blockDim.x + threadIdx.x;
    if (i >= N_NODES * F1) return;
    g_out1[i] = 0.f;
    if (i < N_NODES * H1) { g_m1[i] = __int_as_float(0xff800000); g_s1[i] = 0.f; }
    if (i < N_NODES * C)  { out[i] = 0.f; }
    if (i < N_NODES)      { g_m2[i] = __int_as_float(0xff800000); g_s2[i] = 0.f; }
}

// h1 = concat(x, topo) @ W1.  Block: 16 rows, blockDim (64,16). W1 staged in smem.
__global__ void k_gemm1(const float* __restrict__ x, const float* __restrict__ topo,
                        const float* __restrict__ W1) {
    __shared__ float Ws[K1 * F1];    // 32 KB
    __shared__ float xs[16][K1];     // 8 KB
    int c = threadIdx.x;             // 0..63 output column
    int r = threadIdx.y;             // 0..15 row within block
    int tid = r * 64 + c;
    for (int i = tid; i < K1 * F1; i += 1024) Ws[i] = W1[i];
    int row = blockIdx.x * 16 + r;
    if (row < N_NODES) {
        for (int k = c; k < FEAT; k += 64) xs[r][k] = x[row * FEAT + k];
        if (c < TOPOF) xs[r][FEAT + c] = topo[row * TOPOF + c];
    }
    __syncthreads();
    if (row < N_NODES) {
        float acc = 0.f;
        #pragma unroll
        for (int k = 0; k < K1; k++) acc = fmaf(xs[r][k], Ws[k * F1 + c], acc);
        g_h1[row * F1 + c] = acc;
    }
}

// Attention logits layer1: al_src[n,h] = sum_d h1[n,h,d]*a_src[h,d], same for dst.
__global__ void k_al1(const float* __restrict__ a_src, const float* __restrict__ a_dst) {
    int t = blockIdx.x * blockDim.x + threadIdx.x;
    if (t >= N_NODES * H1) return;
    int n = t >> 3, h = t & 7;
    const float* hp = g_h1 + n * F1 + h * D1;
    float as = 0.f, ad = 0.f;
    #pragma unroll
    for (int k = 0; k < D1; k++) {
        float v = hp[k];
        as = fmaf(v, a_src[h * D1 + k], as);
        ad = fmaf(v, a_dst[h * D1 + k], ad);
    }
    g_als1[t] = as;
    g_ald1[t] = ad;
}

// Pass 1 layer1: per-(dst,head) max of leaky_relu(logit).
__global__ void k_emax1(const int* __restrict__ ei) {
    int t = blockIdx.x * blockDim.x + threadIdx.x;
    int e = t >> 3;
    if (e >= E_TOT) return;
    int head = t & 7;
    int s, d; edge_sd(ei, e, s, d);
    float v = lrelu(g_als1[s * H1 + head] + g_ald1[d * H1 + head]);
    atomic_max_f(&g_m1[d * H1 + head], v);
}

// Pass 2 layer1: unnormalized accumulate. 64 lanes per edge (one per feature dim).
__global__ void k_eacc1(const int* __restrict__ ei) {
    long long t = (long long)blockIdx.x * blockDim.x + threadIdx.x;
    int e = (int)(t >> 6);
    if (e >= E_TOT) return;
    int lane = (int)(t & 63);
    int head = lane >> 3;
    int s, d; edge_sd(ei, e, s, d);
    float logit = g_als1[s * H1 + head] + g_ald1[d * H1 + head];
    float p = __expf(lrelu(logit) - g_m1[d * H1 + head]);
    atomicAdd(&g_out1[d * F1 + lane], p * g_h1[s * F1 + lane]);
    if ((lane & 7) == 0) atomicAdd(&g_s1[d * H1 + head], p);
}

// Normalize + bias + ELU -> h2 (in place in g_out1).
__global__ void k_fin1(const float* __restrict__ b1) {
    int i = blockIdx.x * blockDim.x + threadIdx.x;
    if (i >= N_NODES * F1) return;
    int n = i >> 6, lane = i & 63, head = lane >> 3;
    float v = g_out1[i] / g_s1[n * H1 + head] + b1[lane];
    g_out1[i] = v > 0.f ? v : expm1f(v);
}

// h2lin = h2 @ W2  ([N,64]x[64,40]); one thread per output element, W2 in smem.
__global__ void k_gemm2(const float* __restrict__ W2) {
    __shared__ float Ws[F1 * C];   // 10 KB
    for (int i = threadIdx.x; i < F1 * C; i += blockDim.x) Ws[i] = W2[i];
    __syncthreads();
    int t = blockIdx.x * blockDim.x + threadIdx.x;
    if (t >= N_NODES * C) return;
    int n = t / C, c = t - n * C;
    const float* hrow = g_out1 + n * F1;
    float acc = 0.f;
    #pragma unroll
    for (int k = 0; k < F1; k++) acc = fmaf(hrow[k], Ws[k * C + c], acc);
    g_h2[t] = acc;
}

// Attention logits layer2 (single head over C dims).
__global__ void k_al2(const float* __restrict__ a_src, const float* __restrict__ a_dst) {
    int n = blockIdx.x * blockDim.x + threadIdx.x;
    if (n >= N_NODES) return;
    const float* hp = g_h2 + n * C;
    float as = 0.f, ad = 0.f;
    #pragma unroll
    for (int c = 0; c < C; c++) {
        float v = hp[c];
        as = fmaf(v, a_src[c], as);
        ad = fmaf(v, a_dst[c], ad);
    }
    g_als2[n] = as;
    g_ald2[n] = ad;
}

__global__ void k_emax2(const int* __restrict__ ei) {
    int e = blockIdx.x * blockDim.x + threadIdx.x;
    if (e >= E_TOT) return;
    int s, d; edge_sd(ei, e, s, d);
    atomic_max_f(&g_m2[d], lrelu(g_als2[s] + g_ald2[d]));
}

// Pass 2 layer2: blockDim (40, 8): x = feature dim, y = edge within block.
__global__ void k_eacc2(const int* __restrict__ ei, float* __restrict__ out) {
    int e = blockIdx.x * 8 + threadIdx.y;
    if (e >= E_TOT) return;
    int c = threadIdx.x;
    int s, d; edge_sd(ei, e, s, d);
    float p = __expf(lrelu(g_als2[s] + g_ald2[d]) - g_m2[d]);
    atomicAdd(&out[d * C + c], p * g_h2[s * C + c]);
    if (c == 0) atomicAdd(&g_s2[d], p);
}

// Normalize, add bias, log_softmax over 40 classes. One warp per node, in place.
__global__ void k_final(float* __restrict__ out, const float* __restrict__ b2) {
    int warp = (blockIdx.x * blockDim.x + threadIdx.x) >> 5;
    int lane = threadIdx.x & 31;
    if (warp >= N_NODES) return;
    float inv = 1.f / g_s2[warp];
    float* row = out + (long long)warp * C;
    float v0 = row[lane] * inv + b2[lane];
    float v1 = (lane < C - 32) ? row[32 + lane] * inv + b2[32 + lane]
                               : __int_as_float(0xff800000);
    float m = fmaxf(v0, v1);
    #pragma unroll
    for (int o = 16; o; o >>= 1) m = fmaxf(m, __shfl_xor_sync(0xffffffffu, m, o));
    float sum = __expf(v0 - m) + ((lane < C - 32) ? __expf(v1 - m) : 0.f);
    #pragma unroll
    for (int o = 16; o; o >>= 1) sum += __shfl_xor_sync(0xffffffffu, sum, o);
    float lg = m + logf(sum);
    row[lane] = v0 - lg;
    if (lane < C - 32) row[32 + lane] = v1 - lg;
}

// ---------------- launch ----------------
extern "C" void kernel_launch(void* const* d_in, const int* in_sizes, int n_in,
                              void* d_out, int out_size) {
    const float* x    = (const float*)d_in[0];
    const float* topo = (const float*)d_in[1];
    const int*   ei   = (const int*)  d_in[2];
    const float* W1   = (const float*)d_in[3];
    const float* as1  = (const float*)d_in[4];
    const float* ad1  = (const float*)d_in[5];
    const float* b1   = (const float*)d_in[6];
    const float* W2   = (const float*)d_in[7];
    const float* as2  = (const float*)d_in[8];
    const float* ad2  = (const float*)d_in[9];
    const float* b2   = (const float*)d_in[10];
    float* out = (float*)d_out;

    k_init<<<(N_NODES * F1 + 255) / 256, 256>>>(out);

    dim3 gb1(64, 16);
    k_gemm1<<<(N_NODES + 15) / 16, gb1>>>(x, topo, W1);
    k_al1<<<(N_NODES * H1 + 255) / 256, 256>>>(as1, ad1);

    k_emax1<<<(E_TOT * H1 + 255) / 256, 256>>>(ei);
    {
        long long total = (long long)E_TOT * F1;
        int blocks = (int)((total + 255) / 256);
        k_eacc1<<<blocks, 256>>>(ei);
    }
    k_fin1<<<(N_NODES * F1 + 255) / 256, 256>>>(b1);

    k_gemm2<<<(N_NODES * C + 255) / 256, 256>>>(W2);
    k_al2<<<(N_NODES + 255) / 256, 256>>>(as2, ad2);

    k_emax2<<<(E_TOT + 255) / 256, 256>>>(ei);
    {
        dim3 gb2(40, 8);
        k_eacc2<<<(E_TOT + 7) / 8, gb2>>>(ei, out);
    }
    k_final<<<(N_NODES * 32 + 127) / 128, 128>>>(out, b2);
}

// round 5
// speedup vs baseline: 1.2845x; 1.2845x over previous
#include <cuda_runtime.h>
#include <math.h>

#define N_NODES 50000
#define E_RAW   800000
#define E_TOT   850000   // E_RAW + N_NODES self loops
#define FEAT    120
#define TOPOF   8
#define K1      128      // FEAT + TOPOF
#define F1      64       // H1*D1
#define H1      8
#define D1      8
#define C       40
#define NEG_SLOPE 0.2f

// ---------------- scratch (device globals; no allocs allowed) ----------------
__device__ float g_h1  [N_NODES * F1];   // layer1 linear output [N, 8, 8]
__device__ float g_als1[N_NODES * H1];
__device__ float g_ald1[N_NODES * H1];
__device__ float g_out1[N_NODES * F1];   // layer1 output h2-input (post ELU)
__device__ float g_h2  [N_NODES * C];    // layer2 linear output
__device__ float g_als2[N_NODES];
__device__ float g_ald2[N_NODES];
__device__ int   g_cnt [N_NODES];        // in-degree histogram
__device__ int   g_off [N_NODES + 1];    // CSR row offsets (by dst)
__device__ int   g_cur [N_NODES];        // scatter cursors
__device__ int   g_csrc[E_TOT];          // CSR: src node per incoming edge

// ---------------- helpers ----------------
__device__ __forceinline__ float lrelu(float x) { return x > 0.f ? x : NEG_SLOPE * x; }

__device__ __forceinline__ void edge_sd(const int* __restrict__ ei, int e, int& s, int& d) {
    if (e < E_RAW) { s = ei[e]; d = ei[E_RAW + e]; }
    else           { s = e - E_RAW; d = s; }      // self loop
}

// ---------------- CSR build ----------------
__global__ void k_zero() {
    int i = blockIdx.x * blockDim.x + threadIdx.x;
    if (i < N_NODES) g_cnt[i] = 0;
}

__global__ void k_hist(const int* __restrict__ ei) {
    int e = blockIdx.x * blockDim.x + threadIdx.x;
    if (e >= E_TOT) return;
    int s, d; edge_sd(ei, e, s, d);
    atomicAdd(&g_cnt[d], 1);
}

// Single-block exclusive scan of g_cnt -> g_off, g_cur. 1024 threads.
__global__ void k_scan() {
    __shared__ int sm[1024];
    const int CH = (N_NODES + 1023) / 1024;   // 49
    int t = threadIdx.x;
    int base = t * CH;
    int sum = 0;
    #pragma unroll 4
    for (int j = 0; j < CH; j++) {
        int idx = base + j;
        if (idx < N_NODES) sum += g_cnt[idx];
    }
    sm[t] = sum;
    __syncthreads();
    for (int o = 1; o < 1024; o <<= 1) {
        int v = sm[t];
        int add = (t >= o) ? sm[t - o] : 0;
        __syncthreads();
        sm[t] = v + add;
        __syncthreads();
    }
    int run = (t > 0) ? sm[t - 1] : 0;        // exclusive prefix
    for (int j = 0; j < CH; j++) {
        int idx = base + j;
        if (idx < N_NODES) {
            g_off[idx] = run;
            g_cur[idx] = run;
            run += g_cnt[idx];
        }
    }
    if (t == 0) g_off[N_NODES] = E_TOT;
}

__global__ void k_scatter(const int* __restrict__ ei) {
    int e = blockIdx.x * blockDim.x + threadIdx.x;
    if (e >= E_TOT) return;
    int s, d; edge_sd(ei, e, s, d);
    int pos = atomicAdd(&g_cur[d], 1);
    g_csrc[pos] = s;
}

// ---------------- dense kernels ----------------

// h1 = concat(x, topo) @ W1.  Block: 16 rows, blockDim (64,16). W1 staged in smem.
__global__ void k_gemm1(const float* __restrict__ x, const float* __restrict__ topo,
                        const float* __restrict__ W1) {
    __shared__ float Ws[K1 * F1];    // 32 KB
    __shared__ float xs[16][K1];     // 8 KB
    int c = threadIdx.x;             // 0..63 output column
    int r = threadIdx.y;             // 0..15 row within block
    int tid = r * 64 + c;
    for (int i = tid; i < K1 * F1; i += 1024) Ws[i] = W1[i];
    int row = blockIdx.x * 16 + r;
    if (row < N_NODES) {
        for (int k = c; k < FEAT; k += 64) xs[r][k] = x[row * FEAT + k];
        if (c < TOPOF) xs[r][FEAT + c] = topo[row * TOPOF + c];
    }
    __syncthreads();
    if (row < N_NODES) {
        float acc = 0.f;
        #pragma unroll
        for (int k = 0; k < K1; k++) acc = fmaf(xs[r][k], Ws[k * F1 + c], acc);
        g_h1[row * F1 + c] = acc;
    }
}

// Attention logits layer1.
__global__ void k_al1(const float* __restrict__ a_src, const float* __restrict__ a_dst) {
    int t = blockIdx.x * blockDim.x + threadIdx.x;
    if (t >= N_NODES * H1) return;
    int n = t >> 3, h = t & 7;
    const float* hp = g_h1 + n * F1 + h * D1;
    float as = 0.f, ad = 0.f;
    #pragma unroll
    for (int k = 0; k < D1; k++) {
        float v = hp[k];
        as = fmaf(v, a_src[h * D1 + k], as);
        ad = fmaf(v, a_dst[h * D1 + k], ad);
    }
    g_als1[t] = as;
    g_ald1[t] = ad;
}

// Layer1 aggregation: one warp per dst node. Gather over CSR, registers only.
// Lane owns features lane (head lane>>3) and lane+32 (head lane>>3 + 4).
// Softmax without max-shift (logits are O(1); mathematically identical).
// Fused epilogue: /sum + bias + ELU -> g_out1.
__global__ void k_agg1(const float* __restrict__ b1) {
    int d = (blockIdx.x * blockDim.x + threadIdx.x) >> 5;
    if (d >= N_NODES) return;
    int lane = threadIdx.x & 31;
    int beg = g_off[d], end = g_off[d + 1];
    float ald = (lane < H1) ? g_ald1[d * H1 + lane] : 0.f;
    int h0 = lane >> 3;                   // head of feature `lane`
    float acc0 = 0.f, acc1 = 0.f, psum = 0.f;
    int s = g_csrc[beg];
    for (int i = beg; i < end; i++) {
        int snext = (i + 1 < end) ? g_csrc[i + 1] : 0;
        float p = 0.f;
        if (lane < H1) p = __expf(lrelu(g_als1[s * H1 + lane] + ald));
        float p0 = __shfl_sync(0xffffffffu, p, h0);
        float p1 = __shfl_sync(0xffffffffu, p, h0 + 4);
        const float* hp = g_h1 + s * F1;
        acc0 = fmaf(p0, hp[lane],      acc0);
        acc1 = fmaf(p1, hp[lane + 32], acc1);
        psum += p;
        s = snext;
    }
    float s0 = __shfl_sync(0xffffffffu, psum, h0);
    float s1 = __shfl_sync(0xffffffffu, psum, h0 + 4);
    float v0 = acc0 / s0 + b1[lane];
    float v1 = acc1 / s1 + b1[lane + 32];
    g_out1[d * F1 + lane]      = v0 > 0.f ? v0 : expm1f(v0);
    g_out1[d * F1 + lane + 32] = v1 > 0.f ? v1 : expm1f(v1);
}

// h2 = h @ W2  ([N,64]x[64,40]); 32 rows per block through smem.
__global__ void k_gemm2(const float* __restrict__ W2) {
    __shared__ float Ws[F1 * C];         // 10 KB
    __shared__ float Hs[32][F1 + 1];     // padded vs bank conflicts
    int tid = threadIdx.x;               // 256 threads
    for (int i = tid; i < F1 * C; i += 256) Ws[i] = W2[i];
    int row0 = blockIdx.x * 32;
    for (int i = tid; i < 32 * F1; i += 256) {
        int r = i >> 6, k = i & 63;
        int row = row0 + r;
        Hs[r][k] = (row < N_NODES) ? g_out1[row * F1 + k] : 0.f;
    }
    __syncthreads();
    for (int idx = tid; idx < 32 * C; idx += 256) {
        int r = idx / C, c = idx - r * C;
        int row = row0 + r;
        if (row >= N_NODES) continue;
        float acc = 0.f;
        #pragma unroll
        for (int k = 0; k < F1; k++) acc = fmaf(Hs[r][k], Ws[k * C + c], acc);
        g_h2[row * C + c] = acc;
    }
}

// Attention logits layer2 (single head over C dims).
__global__ void k_al2(const float* __restrict__ a_src, const float* __restrict__ a_dst) {
    int n = blockIdx.x * blockDim.x + threadIdx.x;
    if (n >= N_NODES) return;
    const float* hp = g_h2 + n * C;
    float as = 0.f, ad = 0.f;
    #pragma unroll
    for (int c = 0; c < C; c++) {
        float v = hp[c];
        as = fmaf(v, a_src[c], as);
        ad = fmaf(v, a_dst[c], ad);
    }
    g_als2[n] = as;
    g_ald2[n] = ad;
}

// Layer2 aggregation + bias + log_softmax, fused. One warp per dst node.
// Lane owns class lane, and class lane+32 if lane < 8.
__global__ void k_agg2(float* __restrict__ out, const float* __restrict__ b2) {
    int d = (blockIdx.x * blockDim.x + threadIdx.x) >> 5;
    if (d >= N_NODES) return;
    int lane = threadIdx.x & 31;
    int beg = g_off[d], end = g_off[d + 1];
    float ald = g_ald2[d];
    float acc0 = 0.f, acc1 = 0.f, psum = 0.f;
    int s = g_csrc[beg];
    for (int i = beg; i < end; i++) {
        int snext = (i + 1 < end) ? g_csrc[i + 1] : 0;
        float p = __expf(lrelu(g_als2[s] + ald));
        const float* hp = g_h2 + s * C;
        acc0 = fmaf(p, hp[lane], acc0);
        if (lane < C - 32) acc1 = fmaf(p, hp[lane + 32], acc1);
        psum += p;
        s = snext;
    }
    float inv = 1.f / psum;
    float v0 = acc0 * inv + b2[lane];
    float v1 = (lane < C - 32) ? acc1 * inv + b2[lane + 32]
                               : __int_as_float(0xff800000);
    float m = fmaxf(v0, v1);
    #pragma unroll
    for (int o = 16; o; o >>= 1) m = fmaxf(m, __shfl_xor_sync(0xffffffffu, m, o));
    float sum = __expf(v0 - m) + ((lane < C - 32) ? __expf(v1 - m) : 0.f);
    #pragma unroll
    for (int o = 16; o; o >>= 1) sum += __shfl_xor_sync(0xffffffffu, sum, o);
    float lg = m + logf(sum);
    out[d * C + lane] = v0 - lg;
    if (lane < C - 32) out[d * C + lane + 32] = v1 - lg;
}

// ---------------- launch ----------------
extern "C" void kernel_launch(void* const* d_in, const int* in_sizes, int n_in,
                              void* d_out, int out_size) {
    const float* x    = (const float*)d_in[0];
    const float* topo = (const float*)d_in[1];
    const int*   ei   = (const int*)  d_in[2];
    const float* W1   = (const float*)d_in[3];
    const float* as1  = (const float*)d_in[4];
    const float* ad1  = (const float*)d_in[5];
    const float* b1   = (const float*)d_in[6];
    const float* W2   = (const float*)d_in[7];
    const float* as2  = (const float*)d_in[8];
    const float* ad2  = (const float*)d_in[9];
    const float* b2   = (const float*)d_in[10];
    float* out = (float*)d_out;

    // CSR build (reused by both layers)
    k_zero<<<(N_NODES + 255) / 256, 256>>>();
    k_hist<<<(E_TOT + 255) / 256, 256>>>(ei);
    k_scan<<<1, 1024>>>();
    k_scatter<<<(E_TOT + 255) / 256, 256>>>(ei);

    // Layer 1
    dim3 gb1(64, 16);
    k_gemm1<<<(N_NODES + 15) / 16, gb1>>>(x, topo, W1);
    k_al1<<<(N_NODES * H1 + 255) / 256, 256>>>(as1, ad1);
    k_agg1<<<(N_NODES * 32 + 255) / 256, 256>>>(b1);

    // Layer 2
    k_gemm2<<<(N_NODES + 31) / 32, 256>>>(W2);
    k_al2<<<(N_NODES + 255) / 256, 256>>>(as2, ad2);
    k_agg2<<<(N_NODES * 32 + 255) / 256, 256>>>(out, b2);
}

// round 7
// speedup vs baseline: 3.2725x; 2.5477x over previous
#include <cuda_runtime.h>
#include <math.h>

#define N_NODES 50000
#define E_RAW   800000
#define E_TOT   850000   // E_RAW + N_NODES self loops
#define FEAT    120
#define TOPOF   8
#define K1      128      // FEAT + TOPOF
#define F1      64       // H1*D1
#define H1      8
#define D1      8
#define C       40
#define NEG_SLOPE 0.2f

#define SCAN_B  256
#define SCAN_NB ((N_NODES + SCAN_B - 1) / SCAN_B)   // 196

// ---------------- scratch (device globals; no allocs allowed) ----------------
__device__ float g_h1  [N_NODES * F1];   // layer1 linear output [N, 8, 8]
__device__ float g_als1[N_NODES * H1];
__device__ float g_ald1[N_NODES * H1];
__device__ float g_out1[N_NODES * F1];   // layer1 output (post ELU)
__device__ float g_h2  [N_NODES * C];    // layer2 linear output
__device__ float g_als2[N_NODES];
__device__ float g_ald2[N_NODES];
__device__ int   g_cnt [N_NODES];        // in-degree histogram
__device__ int   g_off [N_NODES + 1];    // CSR row offsets (by dst)
__device__ int   g_cur [N_NODES];        // scatter cursors
__device__ int   g_csrc[E_TOT];          // CSR: src node per incoming edge
__device__ int   g_part[SCAN_B];         // scan block partials

// ---------------- helpers ----------------
__device__ __forceinline__ float lrelu(float x) { return x > 0.f ? x : NEG_SLOPE * x; }

__device__ __forceinline__ void edge_sd(const int* __restrict__ ei, int e, int& s, int& d) {
    if (e < E_RAW) { s = ei[e]; d = ei[E_RAW + e]; }
    else           { s = e - E_RAW; d = s; }      // self loop
}

// ---------------- CSR build ----------------
__global__ void k_zero() {
    int i = blockIdx.x * blockDim.x + threadIdx.x;
    if (i < N_NODES) g_cnt[i] = 0;
}

__global__ void k_hist(const int* __restrict__ ei) {
    int e = blockIdx.x * blockDim.x + threadIdx.x;
    if (e >= E_TOT) return;
    int s, d; edge_sd(ei, e, s, d);
    atomicAdd(&g_cnt[d], 1);
}

// Stage 1: per-block exclusive scan of 256 counts; local result -> g_off, total -> g_part.
__global__ void k_scan1() {
    __shared__ int sm[SCAN_B];
    int t = threadIdx.x;
    int idx = blockIdx.x * SCAN_B + t;
    int v = (idx < N_NODES) ? g_cnt[idx] : 0;
    sm[t] = v;
    __syncthreads();
    #pragma unroll
    for (int o = 1; o < SCAN_B; o <<= 1) {
        int a = sm[t];
        int add = (t >= o) ? sm[t - o] : 0;
        __syncthreads();
        sm[t] = a + add;
        __syncthreads();
    }
    if (idx < N_NODES) g_off[idx] = sm[t] - v;       // exclusive (block-local)
    if (t == SCAN_B - 1) g_part[blockIdx.x] = sm[t]; // block total
}

// Stage 2: single block scans the 196 block totals (exclusive).
__global__ void k_scan2() {
    __shared__ int sm[SCAN_B];
    int t = threadIdx.x;
    int v = (t < SCAN_NB) ? g_part[t] : 0;
    sm[t] = v;
    __syncthreads();
    #pragma unroll
    for (int o = 1; o < SCAN_B; o <<= 1) {
        int a = sm[t];
        int add = (t >= o) ? sm[t - o] : 0;
        __syncthreads();
        sm[t] = a + add;
        __syncthreads();
    }
    if (t < SCAN_NB) g_part[t] = sm[t] - v;          // exclusive
}

// Stage 3: add block offset; fill g_cur; cap sentinel.
__global__ void k_scan3() {
    int idx = blockIdx.x * SCAN_B + threadIdx.x;
    if (idx < N_NODES) {
        int o = g_off[idx] + g_part[blockIdx.x];
        g_off[idx] = o;
        g_cur[idx] = o;
    }
    if (idx == 0) g_off[N_NODES] = E_TOT;
}

__global__ void k_scatter(const int* __restrict__ ei) {
    int e = blockIdx.x * blockDim.x + threadIdx.x;
    if (e >= E_TOT) return;
    int s, d; edge_sd(ei, e, s, d);
    int pos = atomicAdd(&g_cur[d], 1);
    g_csrc[pos] = s;
}

// ---------------- dense kernels ----------------

// h1 = concat(x, topo) @ W1.  64x64 block tile, 4x4 register tile, K chunked by 64.
__global__ void k_gemm1(const float* __restrict__ x, const float* __restrict__ topo,
                        const float* __restrict__ W1) {
    __shared__ float Ws[64][64];       // K-chunk x cols, 16 KB
    __shared__ float Xs[64][65];       // rows x K-chunk, padded, 16.6 KB
    int tx = threadIdx.x;              // 0..15 -> col group
    int ty = threadIdx.y;              // 0..15 -> row group
    int tid = ty * 16 + tx;
    int row0 = blockIdx.x * 64;
    float acc[4][4] = {};

    #pragma unroll
    for (int kc = 0; kc < K1; kc += 64) {
        // stage W chunk: W1[(kc+k)*64 + c]
        for (int i = tid; i < 64 * 64; i += 256) {
            int k = i >> 6, c = i & 63;
            Ws[k][c] = W1[(kc + k) * F1 + c];
        }
        // stage X chunk: rows row0..row0+63, input cols kc..kc+63
        for (int i = tid; i < 64 * 64; i += 256) {
            int r = i >> 6, k = i & 63;
            int row = row0 + r, gk = kc + k;
            float v = 0.f;
            if (row < N_NODES)
                v = (gk < FEAT) ? x[row * FEAT + gk] : topo[row * TOPOF + (gk - FEAT)];
            Xs[r][k] = v;
        }
        __syncthreads();
        #pragma unroll 8
        for (int k = 0; k < 64; k++) {
            float4 b = *(const float4*)&Ws[k][tx * 4];
            float a0 = Xs[ty * 4 + 0][k];
            float a1 = Xs[ty * 4 + 1][k];
            float a2 = Xs[ty * 4 + 2][k];
            float a3 = Xs[ty * 4 + 3][k];
            acc[0][0] = fmaf(a0, b.x, acc[0][0]); acc[0][1] = fmaf(a0, b.y, acc[0][1]);
            acc[0][2] = fmaf(a0, b.z, acc[0][2]); acc[0][3] = fmaf(a0, b.w, acc[0][3]);
            acc[1][0] = fmaf(a1, b.x, acc[1][0]); acc[1][1] = fmaf(a1, b.y, acc[1][1]);
            acc[1][2] = fmaf(a1, b.z, acc[1][2]); acc[1][3] = fmaf(a1, b.w, acc[1][3]);
            acc[2][0] = fmaf(a2, b.x, acc[2][0]); acc[2][1] = fmaf(a2, b.y, acc[2][1]);
            acc[2][2] = fmaf(a2, b.z, acc[2][2]); acc[2][3] = fmaf(a2, b.w, acc[2][3]);
            acc[3][0] = fmaf(a3, b.x, acc[3][0]); acc[3][1] = fmaf(a3, b.y, acc[3][1]);
            acc[3][2] = fmaf(a3, b.z, acc[3][2]); acc[3][3] = fmaf(a3, b.w, acc[3][3]);
        }
        __syncthreads();
    }
    #pragma unroll
    for (int i = 0; i < 4; i++) {
        int row = row0 + ty * 4 + i;
        if (row < N_NODES) {
            float4 v = make_float4(acc[i][0], acc[i][1], acc[i][2], acc[i][3]);
            *(float4*)&g_h1[row * F1 + tx * 4] = v;
        }
    }
}

// Attention logits layer1.
__global__ void k_al1(const float* __restrict__ a_src, const float* __restrict__ a_dst) {
    int t = blockIdx.x * blockDim.x + threadIdx.x;
    if (t >= N_NODES * H1) return;
    int n = t >> 3, h = t & 7;
    const float* hp = g_h1 + n * F1 + h * D1;
    float as = 0.f, ad = 0.f;
    #pragma unroll
    for (int k = 0; k < D1; k++) {
        float v = hp[k];
        as = fmaf(v, a_src[h * D1 + k], as);
        ad = fmaf(v, a_dst[h * D1 + k], ad);
    }
    g_als1[t] = as;
    g_ald1[t] = ad;
}

// Layer1 aggregation: warp per dst node, CSR gather, 1-deep software pipeline.
// Lane owns features lane (head lane>>3) and lane+32 (head lane>>3 + 4).
// Softmax without max-shift (logits are O(1); shift-invariant).
__global__ void k_agg1(const float* __restrict__ b1) {
    int d = (blockIdx.x * blockDim.x + threadIdx.x) >> 5;
    if (d >= N_NODES) return;
    int lane = threadIdx.x & 31;
    int beg = g_off[d], end = g_off[d + 1];
    float ald = (lane < H1) ? g_ald1[d * H1 + lane] : 0.f;
    int h0 = lane >> 3;
    float acc0 = 0.f, acc1 = 0.f, psum = 0.f;

    // prologue prefetch for edge `beg`
    int s = g_csrc[beg];
    float als_n = (lane < H1) ? g_als1[s * H1 + lane] : 0.f;
    float ha_n  = g_h1[s * F1 + lane];
    float hb_n  = g_h1[s * F1 + lane + 32];

    for (int i = beg; i < end; i++) {
        float als = als_n, ha = ha_n, hb = hb_n;
        if (i + 1 < end) {                       // issue next edge's gathers early
            int sn = g_csrc[i + 1];
            als_n = (lane < H1) ? g_als1[sn * H1 + lane] : 0.f;
            ha_n  = g_h1[sn * F1 + lane];
            hb_n  = g_h1[sn * F1 + lane + 32];
        }
        float p = (lane < H1) ? __expf(lrelu(als + ald)) : 0.f;
        float p0 = __shfl_sync(0xffffffffu, p, h0);
        float p1 = __shfl_sync(0xffffffffu, p, h0 + 4);
        acc0 = fmaf(p0, ha, acc0);
        acc1 = fmaf(p1, hb, acc1);
        psum += p;
    }
    float s0 = __shfl_sync(0xffffffffu, psum, h0);
    float s1 = __shfl_sync(0xffffffffu, psum, h0 + 4);
    float v0 = acc0 / s0 + b1[lane];
    float v1 = acc1 / s1 + b1[lane + 32];
    g_out1[d * F1 + lane]      = v0 > 0.f ? v0 : expm1f(v0);
    g_out1[d * F1 + lane + 32] = v1 > 0.f ? v1 : expm1f(v1);
}

// h2 = h @ W2  ([N,64]x[64,40]); 64-row tile, each thread 8 rows x 1 col.
__global__ void k_gemm2(const float* __restrict__ W2) {
    __shared__ float Ws[F1 * C];         // 10 KB
    __shared__ float Hs[64][F1 + 1];     // 16.6 KB
    int tx = threadIdx.x;                // 0..39 col
    int ty = threadIdx.y;                // 0..7  row group
    int tid = ty * 40 + tx;              // 320 threads
    int row0 = blockIdx.x * 64;
    for (int i = tid; i < F1 * C; i += 320) Ws[i] = W2[i];
    for (int i = tid; i < 64 * F1; i += 320) {
        int r = i >> 6, k = i & 63;
        int row = row0 + r;
        Hs[r][k] = (row < N_NODES) ? g_out1[row * F1 + k] : 0.f;
    }
    __syncthreads();
    float acc[8] = {};
    #pragma unroll 8
    for (int k = 0; k < F1; k++) {
        float w = Ws[k * C + tx];
        #pragma unroll
        for (int i = 0; i < 8; i++) acc[i] = fmaf(Hs[ty * 8 + i][k], w, acc[i]);
    }
    #pragma unroll
    for (int i = 0; i < 8; i++) {
        int row = row0 + ty * 8 + i;
        if (row < N_NODES) g_h2[row * C + tx] = acc[i];
    }
}

// Attention logits layer2 (single head over C dims).
__global__ void k_al2(const float* __restrict__ a_src, const float* __restrict__ a_dst) {
    int n = blockIdx.x * blockDim.x + threadIdx.x;
    if (n >= N_NODES) return;
    const float* hp = g_h2 + n * C;
    float as = 0.f, ad = 0.f;
    #pragma unroll
    for (int c = 0; c < C; c++) {
        float v = hp[c];
        as = fmaf(v, a_src[c], as);
        ad = fmaf(v, a_dst[c], ad);
    }
    g_als2[n] = as;
    g_ald2[n] = ad;
}

// Layer2 aggregation + bias + log_softmax, fused. Warp per dst node, pipelined.
__global__ void k_agg2(float* __restrict__ out, const float* __restrict__ b2) {
    int d = (blockIdx.x * blockDim.x + threadIdx.x) >> 5;
    if (d >= N_NODES) return;
    int lane = threadIdx.x & 31;
    int beg = g_off[d], end = g_off[d + 1];
    float ald = g_ald2[d];
    float acc0 = 0.f, acc1 = 0.f, psum = 0.f;

    int s = g_csrc[beg];
    float als_n = g_als2[s];
    float ha_n  = g_h2[s * C + lane];
    float hb_n  = (lane < C - 32) ? g_h2[s * C + lane + 32] : 0.f;

    for (int i = beg; i < end; i++) {
        float als = als_n, ha = ha_n, hb = hb_n;
        if (i + 1 < end) {
            int sn = g_csrc[i + 1];
            als_n = g_als2[sn];
            ha_n  = g_h2[sn * C + lane];
            hb_n  = (lane < C - 32) ? g_h2[sn * C + lane + 32] : 0.f;
        }
        float p = __expf(lrelu(als + ald));
        acc0 = fmaf(p, ha, acc0);
        acc1 = fmaf(p, hb, acc1);
        psum += p;
    }
    float inv = 1.f / psum;
    float v0 = acc0 * inv + b2[lane];
    float v1 = (lane < C - 32) ? acc1 * inv + b2[lane + 32]
                               : __int_as_float(0xff800000);
    float m = fmaxf(v0, v1);
    #pragma unroll
    for (int o = 16; o; o >>= 1) m = fmaxf(m, __shfl_xor_sync(0xffffffffu, m, o));
    float sum = __expf(v0 - m) + ((lane < C - 32) ? __expf(v1 - m) : 0.f);
    #pragma unroll
    for (int o = 16; o; o >>= 1) sum += __shfl_xor_sync(0xffffffffu, sum, o);
    float lg = m + logf(sum);
    out[d * C + lane] = v0 - lg;
    if (lane < C - 32) out[d * C + lane + 32] = v1 - lg;
}

// ---------------- launch ----------------
extern "C" void kernel_launch(void* const* d_in, const int* in_sizes, int n_in,
                              void* d_out, int out_size) {
    const float* x    = (const float*)d_in[0];
    const float* topo = (const float*)d_in[1];
    const int*   ei   = (const int*)  d_in[2];
    const float* W1   = (const float*)d_in[3];
    const float* as1  = (const float*)d_in[4];
    const float* ad1  = (const float*)d_in[5];
    const float* b1   = (const float*)d_in[6];
    const float* W2   = (const float*)d_in[7];
    const float* as2  = (const float*)d_in[8];
    const float* ad2  = (const float*)d_in[9];
    const float* b2   = (const float*)d_in[10];
    float* out = (float*)d_out;

    // CSR build (reused by both layers)
    k_zero<<<(N_NODES + 255) / 256, 256>>>();
    k_hist<<<(E_TOT + 255) / 256, 256>>>(ei);
    k_scan1<<<SCAN_NB, SCAN_B>>>();
    k_scan2<<<1, SCAN_B>>>();
    k_scan3<<<SCAN_NB, SCAN_B>>>();
    k_scatter<<<(E_TOT + 255) / 256, 256>>>(ei);

    // Layer 1
    dim3 tb1(16, 16);
    k_gemm1<<<(N_NODES + 63) / 64, tb1>>>(x, topo, W1);
    k_al1<<<(N_NODES * H1 + 255) / 256, 256>>>(as1, ad1);
    k_agg1<<<(N_NODES * 32 + 255) / 256, 256>>>(b1);

    // Layer 2
    dim3 tb2(40, 8);
    k_gemm2<<<(N_NODES + 63) / 64, tb2>>>(W2);
    k_al2<<<(N_NODES + 255) / 256, 256>>>(as2, ad2);
    k_agg2<<<(N_NODES * 32 + 255) / 256, 256>>>(out, b2);
}